// round 1
// baseline (speedup 1.0000x reference)
#include <cuda_runtime.h>

#define CIN   256
#define HD    512
#define NHEAD 4
#define DDIM  128
#define MAXN  100000

// Scratch (device globals: allocation-free per harness rules)
__device__ __align__(16) float g_q[MAXN * HD];
__device__ __align__(16) float g_k[MAXN * HD];
__device__ __align__(16) float g_v[MAXN * HD];
__device__ __align__(16) float g_kvs[NHEAD * DDIM * DDIM];
__device__ __align__(16) float g_ksum[HD];
__device__ float g_sumsq[2];   // [0]=sum q^2, [1]=sum k^2

// ---------------------------------------------------------------------------
__global__ void zero_scratch() {
    const int total = NHEAD * DDIM * DDIM + HD + 2;
    for (int i = blockIdx.x * blockDim.x + threadIdx.x; i < total;
         i += gridDim.x * blockDim.x) {
        if (i < NHEAD * DDIM * DDIM) g_kvs[i] = 0.f;
        else if (i < NHEAD * DDIM * DDIM + HD) g_ksum[i - NHEAD * DDIM * DDIM] = 0.f;
        else g_sumsq[i - NHEAD * DDIM * DDIM - HD] = 0.f;
    }
}

// ---------------------------------------------------------------------------
// C[N,512] = A[N,256] @ W[256,512] + bias.  BM=BN=128, BK=16, 8x8/thread.
__global__ __launch_bounds__(256) void gemm_bias(
    const float* __restrict__ A, const float* __restrict__ W,
    const float* __restrict__ bias, int which, int N)
{
    __shared__ __align__(16) float As[16][128];
    __shared__ __align__(16) float Bs[16][128];
    float* C = (which == 0) ? g_q : (which == 1) ? g_k : g_v;

    const int r0 = blockIdx.x * 128;
    const int c0 = blockIdx.y * 128;
    const int t  = threadIdx.x;
    const int ty = t >> 4, tx = t & 15;

    float acc[8][8];
#pragma unroll
    for (int i = 0; i < 8; i++)
#pragma unroll
        for (int j = 0; j < 8; j++) acc[i][j] = 0.f;

    for (int kk = 0; kk < CIN; kk += 16) {
        // A tile, stored transposed As[k][m]
#pragma unroll
        for (int s = 0; s < 2; s++) {
            int v = t + s * 256;
            int rowA = v >> 2;
            int c4 = (v & 3) << 2;
            int grow = r0 + rowA;
            float4 f = make_float4(0.f, 0.f, 0.f, 0.f);
            if (grow < N)
                f = *reinterpret_cast<const float4*>(A + (size_t)grow * CIN + kk + c4);
            As[c4 + 0][rowA] = f.x;
            As[c4 + 1][rowA] = f.y;
            As[c4 + 2][rowA] = f.z;
            As[c4 + 3][rowA] = f.w;
        }
        // W tile Bs[k][n]
#pragma unroll
        for (int s = 0; s < 2; s++) {
            int v = t + s * 256;
            int rowB = v >> 5;
            int c4 = (v & 31) << 2;
            *reinterpret_cast<float4*>(&Bs[rowB][c4]) =
                *reinterpret_cast<const float4*>(W + (size_t)(kk + rowB) * HD + c0 + c4);
        }
        __syncthreads();
#pragma unroll
        for (int k = 0; k < 16; k++) {
            float a[8], b[8];
            *reinterpret_cast<float4*>(&a[0]) = *reinterpret_cast<float4*>(&As[k][ty * 8]);
            *reinterpret_cast<float4*>(&a[4]) = *reinterpret_cast<float4*>(&As[k][ty * 8 + 4]);
            *reinterpret_cast<float4*>(&b[0]) = *reinterpret_cast<float4*>(&Bs[k][tx * 8]);
            *reinterpret_cast<float4*>(&b[4]) = *reinterpret_cast<float4*>(&Bs[k][tx * 8 + 4]);
#pragma unroll
            for (int i = 0; i < 8; i++)
#pragma unroll
                for (int j = 0; j < 8; j++)
                    acc[i][j] = fmaf(a[i], b[j], acc[i][j]);
        }
        __syncthreads();
    }

    float bseg[8];
    *reinterpret_cast<float4*>(&bseg[0]) = *reinterpret_cast<const float4*>(bias + c0 + tx * 8);
    *reinterpret_cast<float4*>(&bseg[4]) = *reinterpret_cast<const float4*>(bias + c0 + tx * 8 + 4);
#pragma unroll
    for (int i = 0; i < 8; i++) {
        int row = r0 + ty * 8 + i;
        if (row < N) {
            float4 o0 = make_float4(acc[i][0] + bseg[0], acc[i][1] + bseg[1],
                                    acc[i][2] + bseg[2], acc[i][3] + bseg[3]);
            float4 o1 = make_float4(acc[i][4] + bseg[4], acc[i][5] + bseg[5],
                                    acc[i][6] + bseg[6], acc[i][7] + bseg[7]);
            *reinterpret_cast<float4*>(C + (size_t)row * HD + c0 + tx * 8)     = o0;
            *reinterpret_cast<float4*>(C + (size_t)row * HD + c0 + tx * 8 + 4) = o1;
        }
    }
}

// ---------------------------------------------------------------------------
// Column sums of k (ks_sum) + global sum-of-squares of q and k.
__global__ __launch_bounds__(256) void stats_kernel(int N)
{
    const int t = threadIdx.x;
    float ks0 = 0.f, ks1 = 0.f, sq_q = 0.f, sq_k = 0.f;
    for (int row = blockIdx.x; row < N; row += gridDim.x) {
        const float* kr = g_k + (size_t)row * HD;
        const float* qr = g_q + (size_t)row * HD;
        float k0 = kr[t], k1 = kr[t + 256];
        float q0 = qr[t], q1 = qr[t + 256];
        ks0 += k0; ks1 += k1;
        sq_k = fmaf(k0, k0, sq_k); sq_k = fmaf(k1, k1, sq_k);
        sq_q = fmaf(q0, q0, sq_q); sq_q = fmaf(q1, q1, sq_q);
    }
    atomicAdd(&g_ksum[t], ks0);
    atomicAdd(&g_ksum[t + 256], ks1);

    __shared__ float2 red[256];
    red[t] = make_float2(sq_q, sq_k);
    __syncthreads();
    for (int s = 128; s > 0; s >>= 1) {
        if (t < s) { red[t].x += red[t + s].x; red[t].y += red[t + s].y; }
        __syncthreads();
    }
    if (t == 0) {
        atomicAdd(&g_sumsq[0], red[0].x);
        atomicAdd(&g_sumsq[1], red[0].y);
    }
}

// ---------------------------------------------------------------------------
// kvs[h,m,d] += sum_n k[n,h,m] * v[n,h,d]   (split-K over N, atomicAdd)
__global__ __launch_bounds__(256) void kvs_kernel(int N)
{
    __shared__ __align__(16) float Ks[16][128];
    __shared__ __align__(16) float Vs[16][128];
    const int h = blockIdx.y;
    const int nchunks = gridDim.x;
    const int chunk = (N + nchunks - 1) / nchunks;
    const int n0 = blockIdx.x * chunk;
    const int n1 = min(n0 + chunk, N);
    const int t = threadIdx.x;
    const int ty = t >> 4, tx = t & 15;

    float acc[8][8];
#pragma unroll
    for (int i = 0; i < 8; i++)
#pragma unroll
        for (int j = 0; j < 8; j++) acc[i][j] = 0.f;

    for (int nn = n0; nn < n1; nn += 16) {
#pragma unroll
        for (int s = 0; s < 2; s++) {
            int v = t + s * 256;
            int r = v >> 5;
            int c4 = (v & 31) << 2;
            int grow = nn + r;
            float4 fk = make_float4(0.f, 0.f, 0.f, 0.f);
            float4 fv = fk;
            if (grow < n1) {
                fk = *reinterpret_cast<const float4*>(g_k + (size_t)grow * HD + h * DDIM + c4);
                fv = *reinterpret_cast<const float4*>(g_v + (size_t)grow * HD + h * DDIM + c4);
            }
            *reinterpret_cast<float4*>(&Ks[r][c4]) = fk;
            *reinterpret_cast<float4*>(&Vs[r][c4]) = fv;
        }
        __syncthreads();
#pragma unroll
        for (int k = 0; k < 16; k++) {
            float a[8], b[8];
            *reinterpret_cast<float4*>(&a[0]) = *reinterpret_cast<float4*>(&Ks[k][ty * 8]);
            *reinterpret_cast<float4*>(&a[4]) = *reinterpret_cast<float4*>(&Ks[k][ty * 8 + 4]);
            *reinterpret_cast<float4*>(&b[0]) = *reinterpret_cast<float4*>(&Vs[k][tx * 8]);
            *reinterpret_cast<float4*>(&b[4]) = *reinterpret_cast<float4*>(&Vs[k][tx * 8 + 4]);
#pragma unroll
            for (int i = 0; i < 8; i++)
#pragma unroll
                for (int j = 0; j < 8; j++)
                    acc[i][j] = fmaf(a[i], b[j], acc[i][j]);
        }
        __syncthreads();
    }

    float* dst = g_kvs + h * DDIM * DDIM;
#pragma unroll
    for (int i = 0; i < 8; i++)
#pragma unroll
        for (int j = 0; j < 8; j++)
            atomicAdd(dst + (ty * 8 + i) * DDIM + tx * 8 + j, acc[i][j]);
}

// ---------------------------------------------------------------------------
// out[n,d] = 0.25 * sum_h ( q[n,h,:]·kvs[h,:,d]·inv + N·v[n,h,d] ) * rden[n,h]
// rden = 1/(q[n,h,:]·ksum[h]·inv + N).  rden*inv folded into Q tile at load.
__global__ __launch_bounds__(256) void final_kernel(float* __restrict__ out, int N)
{
    __shared__ __align__(16) float Qs[16][128];
    __shared__ __align__(16) float KVs[16][128];
    __shared__ float rden[128];
    __shared__ float ksum_s[128];

    const int r0 = blockIdx.x * 128;
    const int t  = threadIdx.x;
    const int ty = t >> 4, tx = t & 15;
    const float inv = rsqrtf(g_sumsq[0]) * rsqrtf(g_sumsq[1]);
    const float Nf  = (float)N;

    float oacc[8][8];
#pragma unroll
    for (int i = 0; i < 8; i++)
#pragma unroll
        for (int j = 0; j < 8; j++) oacc[i][j] = 0.f;

    for (int h = 0; h < NHEAD; h++) {
        if (t < 128) ksum_s[t] = g_ksum[h * DDIM + t];
        __syncthreads();
        if (t < 128) {
            int row = r0 + t;
            float d = 0.f;
            if (row < N) {
                const float* qr = g_q + (size_t)row * HD + h * DDIM;
#pragma unroll 8
                for (int m = 0; m < DDIM; m++) d = fmaf(qr[m], ksum_s[m], d);
            }
            rden[t] = 1.0f / (d * inv + Nf);
        }
        __syncthreads();

        for (int kk = 0; kk < DDIM; kk += 16) {
            // Q tile transposed, pre-scaled by rden[row]*inv
#pragma unroll
            for (int s = 0; s < 2; s++) {
                int v = t + s * 256;
                int rowA = v >> 2;
                int c4 = (v & 3) << 2;
                int grow = r0 + rowA;
                float4 f = make_float4(0.f, 0.f, 0.f, 0.f);
                if (grow < N)
                    f = *reinterpret_cast<const float4*>(g_q + (size_t)grow * HD + h * DDIM + kk + c4);
                float sc = rden[rowA] * inv;
                Qs[c4 + 0][rowA] = f.x * sc;
                Qs[c4 + 1][rowA] = f.y * sc;
                Qs[c4 + 2][rowA] = f.z * sc;
                Qs[c4 + 3][rowA] = f.w * sc;
            }
#pragma unroll
            for (int s = 0; s < 2; s++) {
                int v = t + s * 256;
                int r = v >> 5;
                int c4 = (v & 31) << 2;
                *reinterpret_cast<float4*>(&KVs[r][c4]) =
                    *reinterpret_cast<const float4*>(g_kvs + h * DDIM * DDIM + (size_t)(kk + r) * DDIM + c4);
            }
            __syncthreads();
#pragma unroll
            for (int k = 0; k < 16; k++) {
                float a[8], b[8];
                *reinterpret_cast<float4*>(&a[0]) = *reinterpret_cast<float4*>(&Qs[k][ty * 8]);
                *reinterpret_cast<float4*>(&a[4]) = *reinterpret_cast<float4*>(&Qs[k][ty * 8 + 4]);
                *reinterpret_cast<float4*>(&b[0]) = *reinterpret_cast<float4*>(&KVs[k][tx * 8]);
                *reinterpret_cast<float4*>(&b[4]) = *reinterpret_cast<float4*>(&KVs[k][tx * 8 + 4]);
#pragma unroll
                for (int i = 0; i < 8; i++)
#pragma unroll
                    for (int j = 0; j < 8; j++)
                        oacc[i][j] = fmaf(a[i], b[j], oacc[i][j]);
            }
            __syncthreads();
        }

        // + N * v[n,h,d] * rden
#pragma unroll
        for (int i = 0; i < 8; i++) {
            int row = r0 + ty * 8 + i;
            if (row < N) {
                float nrd = Nf * rden[ty * 8 + i];
                const float* vr = g_v + (size_t)row * HD + h * DDIM + tx * 8;
                float4 v0 = *reinterpret_cast<const float4*>(vr);
                float4 v1 = *reinterpret_cast<const float4*>(vr + 4);
                oacc[i][0] = fmaf(nrd, v0.x, oacc[i][0]);
                oacc[i][1] = fmaf(nrd, v0.y, oacc[i][1]);
                oacc[i][2] = fmaf(nrd, v0.z, oacc[i][2]);
                oacc[i][3] = fmaf(nrd, v0.w, oacc[i][3]);
                oacc[i][4] = fmaf(nrd, v1.x, oacc[i][4]);
                oacc[i][5] = fmaf(nrd, v1.y, oacc[i][5]);
                oacc[i][6] = fmaf(nrd, v1.z, oacc[i][6]);
                oacc[i][7] = fmaf(nrd, v1.w, oacc[i][7]);
            }
        }
        __syncthreads();
    }

#pragma unroll
    for (int i = 0; i < 8; i++) {
        int row = r0 + ty * 8 + i;
        if (row < N) {
            float4 o0 = make_float4(0.25f * oacc[i][0], 0.25f * oacc[i][1],
                                    0.25f * oacc[i][2], 0.25f * oacc[i][3]);
            float4 o1 = make_float4(0.25f * oacc[i][4], 0.25f * oacc[i][5],
                                    0.25f * oacc[i][6], 0.25f * oacc[i][7]);
            *reinterpret_cast<float4*>(out + (size_t)row * DDIM + tx * 8)     = o0;
            *reinterpret_cast<float4*>(out + (size_t)row * DDIM + tx * 8 + 4) = o1;
        }
    }
}

// ---------------------------------------------------------------------------
extern "C" void kernel_launch(void* const* d_in, const int* in_sizes, int n_in,
                              void* d_out, int out_size)
{
    const float* q_in = (const float*)d_in[0];
    const float* k_in = (const float*)d_in[1];
    const float* v_in = (const float*)d_in[2];
    const float* Wq   = (const float*)d_in[3];
    const float* bq   = (const float*)d_in[4];
    const float* Wk   = (const float*)d_in[5];
    const float* bk   = (const float*)d_in[6];
    const float* Wv   = (const float*)d_in[7];
    const float* bv   = (const float*)d_in[8];
    float* out = (float*)d_out;

    const int N = in_sizes[0] / CIN;
    const int rowBlocks = (N + 127) / 128;

    zero_scratch<<<64, 256>>>();
    gemm_bias<<<dim3(rowBlocks, 4), 256>>>(q_in, Wq, bq, 0, N);
    gemm_bias<<<dim3(rowBlocks, 4), 256>>>(k_in, Wk, bk, 1, N);
    gemm_bias<<<dim3(rowBlocks, 4), 256>>>(v_in, Wv, bv, 2, N);
    stats_kernel<<<512, 256>>>(N);
    kvs_kernel<<<dim3(128, NHEAD), 256>>>(N);
    final_kernel<<<rowBlocks, 256>>>(out, N);
}